// round 17
// baseline (speedup 1.0000x reference)
#include <cuda_runtime.h>
#include <cuda_fp16.h>
#include <cstdint>
#include <math.h>

#define BB   2
#define TT   1024
#define CC   1024
#define HH   16
#define DD   64
#define MM   (BB*TT)
#define KK   (2*CC)
#define NN   (2*CC)

// ---------------------------------------------------------------------------
// Scratch (__device__ globals), fp16 hi-only activations
// ---------------------------------------------------------------------------
__device__ __half g_xh[(size_t)MM * KK];       // x hi / attn-out hi
__device__ __half g_wh[4 * (size_t)NN * KK];   // weights hi
// q/k/v in [B*H][T][128] fp16 (interleaved re/im)
__device__ __half g_qh[(size_t)32 * TT * 128];
__device__ __half g_kh[(size_t)32 * TT * 128];
__device__ __half g_vh[(size_t)32 * TT * 128];

// ---------------------------------------------------------------------------
// Helpers
// ---------------------------------------------------------------------------
__device__ __forceinline__ uint32_t smem_u32(const void* p) {
    uint32_t a;
    asm("{ .reg .u64 t; cvta.to.shared.u64 t, %1; cvt.u32.u64 %0, t; }"
        : "=r"(a) : "l"(p));
    return a;
}
__device__ __forceinline__ uint32_t sw128(uint32_t o) { return o ^ ((o >> 3) & 0x70); }

__device__ __forceinline__ void ldsm_x4(uint32_t& r0, uint32_t& r1, uint32_t& r2,
                                        uint32_t& r3, uint32_t addr) {
    asm volatile("ldmatrix.sync.aligned.m8n8.x4.shared.b16 {%0,%1,%2,%3}, [%4];"
                 : "=r"(r0), "=r"(r1), "=r"(r2), "=r"(r3) : "r"(addr));
}
__device__ __forceinline__ void ldsm_x4_t(uint32_t& r0, uint32_t& r1, uint32_t& r2,
                                          uint32_t& r3, uint32_t addr) {
    asm volatile("ldmatrix.sync.aligned.m8n8.x4.trans.shared.b16 {%0,%1,%2,%3}, [%4];"
                 : "=r"(r0), "=r"(r1), "=r"(r2), "=r"(r3) : "r"(addr));
}
// NOT volatile: ptxas may schedule freely.
__device__ __forceinline__ void mma_f16(float* c, const uint32_t* a, const uint32_t* b) {
    asm("mma.sync.aligned.m16n8k16.row.col.f32.f16.f16.f32 "
        "{%0,%1,%2,%3},{%4,%5,%6,%7},{%8,%9},{%0,%1,%2,%3};"
        : "+f"(c[0]), "+f"(c[1]), "+f"(c[2]), "+f"(c[3])
        : "r"(a[0]), "r"(a[1]), "r"(a[2]), "r"(a[3]), "r"(b[0]), "r"(b[1]));
}
__device__ __forceinline__ uint32_t swapneg(uint32_t b) {
    uint32_t r;
    asm("prmt.b32 %0, %1, %1, 0x1032;" : "=r"(r) : "r"(b));
    return r ^ 0x00008000u;
}
__device__ __forceinline__ uint32_t packh(__half x, __half y) {
    __half2 t = __halves2half2(x, y);
    return *(uint32_t*)&t;
}
__device__ __forceinline__ void cp16(uint32_t smem, const void* g) {
    asm volatile("cp.async.cg.shared.global [%0], [%1], 16;"
                 :: "r"(smem), "l"(g) : "memory");
}
__device__ __forceinline__ void cp_commit() {
    asm volatile("cp.async.commit_group;" ::: "memory");
}
template <int N> __device__ __forceinline__ void cp_wait() {
    asm volatile("cp.async.wait_group %0;" :: "n"(N) : "memory");
}

// ---------------------------------------------------------------------------
// fp32 -> fp16 (hi only) of the input activation
// ---------------------------------------------------------------------------
__global__ __launch_bounds__(256) void conv_x_kernel(const float4* __restrict__ xin) {
    size_t i = (size_t)blockIdx.x * 256 + threadIdx.x;
    float4 v = xin[i];
    ((__half2*)g_xh)[2*i]   = __halves2half2(__float2half_rn(v.x), __float2half_rn(v.y));
    ((__half2*)g_xh)[2*i+1] = __halves2half2(__float2half_rn(v.z), __float2half_rn(v.w));
}

// Expand complex weight -> real [2N,2K], fp16 hi only
__global__ __launch_bounds__(256) void conv_w_kernel(
    const float2* __restrict__ w0, const float2* __restrict__ w1,
    const float2* __restrict__ w2, const float2* __restrict__ w3) {
    int z = blockIdx.z;
    const float2* W = (z == 0) ? w0 : (z == 1) ? w1 : (z == 2) ? w2 : w3;
    size_t e = (size_t)blockIdx.x * 256 + threadIdx.x;
    float2 w = W[e];
    int n = (int)(e >> 10), k = (int)(e & 1023);
    __half wr = __float2half_rn(w.x);
    __half wi = __float2half_rn(w.y);
    __half nwi = __float2half_rn(-w.y);
    size_t base = (size_t)z * NN * KK;
    size_t r0 = base + (size_t)(2*n)   * KK + 2*k;
    size_t r1 = base + (size_t)(2*n+1) * KK + 2*k;
    *(__half2*)(g_wh + r0) = __halves2half2(wr, nwi);
    *(__half2*)(g_wh + r1) = __halves2half2(wi, wr);
}

// ---------------------------------------------------------------------------
// mma.sync fp16 1-pass GEMM, 3-stage cp.async pipeline, 2 CTAs/SM.
// C = Ah.Bh^T.  CTA 128x128, K tiles 64. 8 warps (2 x 4), warp tile 64x32.
// ---------------------------------------------------------------------------
#define GBM 128
#define GBN 128
#define GBK 64
#define NKC (KK / GBK)        // 32 k-chunks
#define STG_SZ 32768          // per-stage: AH 16K | BH 16K
#define GEMM_SMEM_SZ (3 * STG_SZ)

__global__ __launch_bounds__(256, 2) void gemm_mma_kernel(
    const float2* __restrict__ BiasQ, const float2* __restrict__ BiasK,
    const float2* __restrict__ BiasV, float2* __restrict__ OutParam, int fused)
{
    extern __shared__ char smem[];
    const uint32_t sb = smem_u32(smem);
    const int tid  = threadIdx.x;
    const int lane = tid & 31, wid = tid >> 5;
    const int wm = wid & 1;
    const int wn = wid >> 1;
    const int m0 = blockIdx.y * GBM;
    const int n0 = blockIdx.x * GBN;

    int widx, outsel, rope;
    const float2* Bias;
    if (fused) {
        widx = blockIdx.z; outsel = widx; rope = (widx < 2);
        Bias = (widx == 0) ? BiasQ : (widx == 1) ? BiasK : BiasV;
    } else {
        widx = 3; outsel = 3; rope = 0; Bias = BiasQ;
    }
    const __half* __restrict__ Wh = g_wh + (size_t)widx * NN * KK;

    float acc[4][4][4];
#pragma unroll
    for (int mi = 0; mi < 4; mi++)
#pragma unroll
        for (int ni = 0; ni < 4; ni++)
#pragma unroll
            for (int r = 0; r < 4; r++) acc[mi][ni][r] = 0.f;

    const int rowL = tid >> 1;
    const int segL = (tid & 1) * 4;
    const size_t arow = (size_t)(m0 + rowL) * KK;
    const size_t brow = (size_t)(n0 + rowL) * KK;

    auto issue_stage = [&](int stage, int kc) {
        const uint32_t s0 = sb + stage * STG_SZ;
        const size_t ka = arow + (size_t)kc * GBK;
        const size_t kb = brow + (size_t)kc * GBK;
#pragma unroll
        for (int i = 0; i < 4; i++) {
            const uint32_t so = sw128(rowL * 128 + (segL + i) * 16);
            cp16(s0 + 0     + so, g_xh + ka + (segL + i) * 8);
            cp16(s0 + 16384 + so, Wh   + kb + (segL + i) * 8);
        }
        cp_commit();
    };

    const int aRow = (lane & 15);
    const int aCol = (lane >> 4) * 16;
    const int bRow = (lane & 7) + 8 * (lane >> 4);
    const int bCol = ((lane >> 3) & 1) * 16;

    issue_stage(0, 0);
    issue_stage(1, 1);

    for (int kc = 0; kc < NKC; kc++) {
        if (kc == NKC - 1) cp_wait<0>(); else cp_wait<1>();
        __syncthreads();   // chunk kc visible; all warps done reading stage (kc+2)%3
        if (kc + 2 < NKC) issue_stage((kc + 2) % 3, kc + 2);

        const uint32_t s0 = sb + (kc % 3) * STG_SZ;
#pragma unroll
        for (int ks = 0; ks < 4; ks++) {
            uint32_t ah[4][4], bh[4][2];
#pragma unroll
            for (int mi = 0; mi < 4; mi++) {
                const uint32_t off = sw128((wm * 64 + mi * 16 + aRow) * 128 +
                                           ks * 32 + aCol);
                ldsm_x4(ah[mi][0], ah[mi][1], ah[mi][2], ah[mi][3], s0 + off);
            }
#pragma unroll
            for (int np = 0; np < 2; np++) {
                const uint32_t off = sw128((wn * 32 + np * 16 + bRow) * 128 +
                                           ks * 32 + bCol);
                uint32_t r0, r1, r2, r3;
                ldsm_x4(r0, r1, r2, r3, s0 + 16384 + off);
                bh[np*2][0] = r0; bh[np*2][1] = r1;
                bh[np*2+1][0] = r2; bh[np*2+1][1] = r3;
            }
#pragma unroll
            for (int mi = 0; mi < 4; mi++)
#pragma unroll
                for (int ni = 0; ni < 4; ni++)
                    mma_f16(acc[mi][ni], ah[mi], bh[ni]);
        }
    }

    // Epilogue
    __syncthreads();
    const int mbase = m0 + wm * 64 + (lane >> 2);
    const int cb = n0 + wn * 32 + 2 * (lane & 3);
#pragma unroll
    for (int ni = 0; ni < 4; ni++) {
        const int c = cb + ni * 8;
        const int n = c >> 1;
        const float2 bias = Bias[n];
        const int h = n >> 6, d = n & 63;
        float invf = 0.f;
        if (rope) invf = powf(10000.f, -(float)d * (1.f / 64.f));
#pragma unroll
        for (int mi = 0; mi < 4; mi++)
#pragma unroll
            for (int rr = 0; rr < 2; rr++) {
                const int m = mbase + mi * 16 + rr * 8;
                float re = acc[mi][ni][rr * 2 + 0] + bias.x;
                float im = acc[mi][ni][rr * 2 + 1] + bias.y;
                const int b = m >> 10, t = m & (TT - 1);
                if (rope) {
                    float s, cs;
                    sincosf((float)t * invf, &s, &cs);
                    float r2 = re * cs - im * s;
                    im = re * s + im * cs;
                    re = r2;
                }
                if (outsel == 3) {
                    OutParam[(size_t)m * CC + n] = make_float2(re, im);
                } else {
                    uint32_t hi = packh(__float2half_rn(re), __float2half_rn(im));
                    size_t idx = (((size_t)(b * HH + h) * TT + t) * 128 + 2 * d);
                    if (outsel == 0)      *(uint32_t*)(g_qh + idx) = hi;
                    else if (outsel == 1) *(uint32_t*)(g_kh + idx) = hi;
                    else                  *(uint32_t*)(g_vh + idx) = hi;
                }
            }
    }
}

// ---------------------------------------------------------------------------
// Tensor-core flash attention: 128-thread CTAs (4 warps, 64 q-rows),
// 2 CTAs/SM for barrier/stall overlap. 2-stage cp.async K/V pipe.
//   S_re = Qh.Kh^T ; -S_im = Qh'.Kh^T (Q' = swapneg(Q), precomputed in smem)
//   P = exp(|S|/8) (fixed shift; |S|/8 bounded, exp safe)
//   O = P.Vh ; row sums reduced once at the epilogue.
// smem layout (FIXED from R15: Q region is 16KB, not 8KB):
//   [0, 16K)      Q      (two 8KB half-banks)
//   [16K, 32K)    Q-swap (two 8KB half-banks)
//   [32K, 96K)    2 stages x (K_H 16K | V_H 16K)
// ---------------------------------------------------------------------------
#define ATQ_H 0
#define ATQ_S 16384
#define ATSTG 32768
#define ASTG_SZ 32768        // K_H 16K | V_H 16K
#define ATTN_SMEM2 (ATSTG + 2 * ASTG_SZ)   // 98304 -> 2 CTAs/SM fits (192K)

__global__ __launch_bounds__(128, 2) void attn_mma_kernel()
{
    extern __shared__ char sm[];
    const uint32_t sb = smem_u32(sm);
    const int tid = threadIdx.x, lane = tid & 31, wid = tid >> 5;  // 4 warps
    const int bh = blockIdx.y;
    const int t0 = blockIdx.x * 64;
    const size_t gbase = (size_t)bh * TT * 128;

    const int krow = tid >> 1, kq = (tid & 1) * 8;   // 64 rows x 16 segs, 128 thr

    auto issue_chunk = [&](int stage, int c) {
        const uint32_t s0 = sb + ATSTG + stage * ASTG_SZ;
        const size_t g = gbase + (size_t)(c * 64 + krow) * 128 + kq * 8;
#pragma unroll
        for (int i = 0; i < 8; i++) {
            const int seg = kq + i;
            const uint32_t so = (seg >> 3) * 8192 + sw128(krow * 128 + (seg & 7) * 16);
            cp16(s0 + 0     + so, g_kh + g + i * 8);
            cp16(s0 + 16384 + so, g_vh + g + i * 8);
        }
        cp_commit();
    };

    issue_chunk(0, 0);

    // Q tile (64 rows x 128 cols) + swapped-Q tile, two 64-col half-banks each
    {
        const int row = tid >> 1, half = tid & 1;    // rows 0..63
        const size_t g = gbase + (size_t)(t0 + row) * 128 + half * 64;
#pragma unroll
        for (int i = 0; i < 8; i++) {
            uint4 vh = *(const uint4*)(g_qh + g + i * 8);
            uint32_t so = half * 8192 + sw128(row * 128 + i * 16);
            *(uint4*)(sm + ATQ_H + so) = vh;
            uint4 vs;
            vs.x = swapneg(vh.x); vs.y = swapneg(vh.y);
            vs.z = swapneg(vh.z); vs.w = swapneg(vh.w);
            *(uint4*)(sm + ATQ_S + so) = vs;
        }
    }

    float o[16][4];
#pragma unroll
    for (int i = 0; i < 16; i++)
#pragma unroll
        for (int j = 0; j < 4; j++) o[i][j] = 0.f;
    float lrow[2] = {0.f, 0.f};

    const int aRow = lane & 15, aCol = (lane >> 4) * 16;
    const int bRow = (lane & 7) + 8 * (lane >> 4), bCol = ((lane >> 3) & 1) * 16;
    const int vS = ((lane >> 3) & 1) * 8 + (lane & 7);
    const int vD = (lane >> 4) * 8;

    for (int c = 0; c < 16; c++) {
        const int cur = c & 1;
        if (c + 1 < 16) {
            issue_chunk(cur ^ 1, c + 1);
            cp_wait<1>();
        } else {
            cp_wait<0>();
        }
        __syncthreads();
        const uint32_t stg = sb + ATSTG + cur * ASTG_SZ;

        // ---- S_re and -S_im ----
        float sre[8][4], sim[8][4];
#pragma unroll
        for (int i = 0; i < 8; i++)
#pragma unroll
            for (int j = 0; j < 4; j++) { sre[i][j] = 0.f; sim[i][j] = 0.f; }

#pragma unroll
        for (int ks = 0; ks < 8; ks++) {
            const uint32_t qoff = (ks >> 2) * 8192 +
                sw128((wid * 16 + aRow) * 128 + (ks & 3) * 32 + aCol);
            uint32_t ah[4], aq[4];
            ldsm_x4(ah[0], ah[1], ah[2], ah[3], sb + ATQ_H + qoff);
            ldsm_x4(aq[0], aq[1], aq[2], aq[3], sb + ATQ_S + qoff);
#pragma unroll
            for (int np = 0; np < 4; np++) {
                const uint32_t koff = (ks >> 2) * 8192 +
                    sw128((np * 16 + bRow) * 128 + (ks & 3) * 32 + bCol);
                uint32_t h0, h1, h2, h3;
                ldsm_x4(h0, h1, h2, h3, stg + koff);
                uint32_t b0[2] = {h0, h1}, b1[2] = {h2, h3};
                mma_f16(sre[np*2],   ah, b0);
                mma_f16(sre[np*2+1], ah, b1);
                mma_f16(sim[np*2],   aq, b0);
                mma_f16(sim[np*2+1], aq, b1);
            }
        }

        // ---- P = exp(|S|/8), accumulate row partials ----
#pragma unroll
        for (int ni = 0; ni < 8; ni++)
#pragma unroll
            for (int j = 0; j < 4; j++) {
                float a = __fsqrt_rn(sre[ni][j] * sre[ni][j] +
                                     sim[ni][j] * sim[ni][j]) * 0.125f;
                float e = __expf(a);
                sre[ni][j] = e;
                lrow[j >> 1] += e;
            }

        // ---- O += P.Vh ----
#pragma unroll
        for (int kk = 0; kk < 4; kk++) {
            uint32_t pah[4];
#pragma unroll
            for (int half = 0; half < 2; half++) {
                const int ni = 2 * kk + half;
                pah[half * 2 + 0] = packh(__float2half_rn(sre[ni][0]),
                                          __float2half_rn(sre[ni][1]));
                pah[half * 2 + 1] = packh(__float2half_rn(sre[ni][2]),
                                          __float2half_rn(sre[ni][3]));
            }
#pragma unroll
            for (int ng = 0; ng < 8; ng++) {
                const uint32_t voff = (ng >> 2) * 8192 +
                    sw128((kk * 16 + vS) * 128 + ((ng & 3) * 16 + vD) * 2);
                uint32_t v0, v1, v2, v3;
                ldsm_x4_t(v0, v1, v2, v3, stg + 16384 + voff);
                uint32_t vb0[2] = {v0, v1}, vb1[2] = {v2, v3};
                mma_f16(o[ng*2],   pah, vb0);
                mma_f16(o[ng*2+1], pah, vb1);
            }
        }
        __syncthreads();   // all warps done with stage 'cur' before it is refilled
    }

    // ---- epilogue: single quad-reduction of row sums, normalize, write ----
#pragma unroll
    for (int off = 1; off < 4; off <<= 1) {
        lrow[0] += __shfl_xor_sync(0xffffffffu, lrow[0], off);
        lrow[1] += __shfl_xor_sync(0xffffffffu, lrow[1], off);
    }
    const int b = bh >> 4, h = bh & 15;
    const float inv0 = 1.f / lrow[0], inv1 = 1.f / lrow[1];
    const int r = lane >> 2, tc2 = (lane & 3) * 2;
    const int mrow0 = b * TT + t0 + wid * 16 + r;
#pragma unroll
    for (int ni = 0; ni < 16; ni++) {
        const int col = h * 128 + ni * 8 + tc2;
#pragma unroll
        for (int rr = 0; rr < 2; rr++) {
            const int m = mrow0 + rr * 8;
            const float inv = rr ? inv1 : inv0;
            float re = o[ni][rr * 2 + 0] * inv;
            float im = o[ni][rr * 2 + 1] * inv;
            size_t idx = (size_t)m * KK + col;
            *(uint32_t*)(g_xh + idx) = packh(__float2half_rn(re),
                                             __float2half_rn(im));
        }
    }
}

// ---------------------------------------------------------------------------
// kernel_launch
// ---------------------------------------------------------------------------
extern "C" void kernel_launch(void* const* d_in, const int* in_sizes, int n_in,
                              void* d_out, int out_size)
{
    (void)in_sizes; (void)n_in; (void)out_size;
    const float4* x  = (const float4*)d_in[0];
    const float2* wq = (const float2*)d_in[1];
    const float2* bq = (const float2*)d_in[2];
    const float2* wk = (const float2*)d_in[3];
    const float2* bk = (const float2*)d_in[4];
    const float2* wv = (const float2*)d_in[5];
    const float2* bv = (const float2*)d_in[6];
    const float2* wo = (const float2*)d_in[7];
    const float2* bo = (const float2*)d_in[8];
    float2* out = (float2*)d_out;

    cudaFuncSetAttribute(gemm_mma_kernel,
                         cudaFuncAttributeMaxDynamicSharedMemorySize, GEMM_SMEM_SZ);
    cudaFuncSetAttribute(attn_mma_kernel,
                         cudaFuncAttributeMaxDynamicSharedMemorySize, ATTN_SMEM2);

    const int convx_blocks = (MM * KK / 4) / 256;   // 4096
    const int convw_blocks = (CC * CC) / 256;       // 4096

    conv_x_kernel<<<convx_blocks, 256>>>(x);
    conv_w_kernel<<<dim3(convw_blocks, 1, 4), 256>>>(wq, wk, wv, wo);

    gemm_mma_kernel<<<dim3(NN / GBN, MM / GBM, 3), 256, GEMM_SMEM_SZ>>>(
        bq, bk, bv, nullptr, 1);

    attn_mma_kernel<<<dim3(TT / 64, BB * HH), 128, ATTN_SMEM2>>>();

    gemm_mma_kernel<<<dim3(NN / GBN, MM / GBM, 1), 256, GEMM_SMEM_SZ>>>(
        bo, nullptr, nullptr, out, 0);
}